// round 7
// baseline (speedup 1.0000x reference)
#include <cuda_runtime.h>

#define NP 400000
#define SXYZ 11264000
#define SYZ 16000
#define SZ 20
#define NWORDS 704000
#define SCAN_BLOCKS 688

#define OFF0 (0.05f)
#define OFF1 (0.05f - 40.0f)
#define OFF2 (0.1f - 3.0f)

__device__ unsigned g_bits[NWORDS];
__device__ unsigned g_wpre[NWORDS];
__device__ unsigned g_bsum[SCAN_BLOCKS];
__device__ unsigned g_boff[SCAN_BLOCKS];
__device__ int      g_keys[NP];
__device__ int      g_inv[NP];
__device__ int      g_cnt[NP];
__device__ float    g_sums[NP * 3];
__device__ float    g_y0[(size_t)64 * NP];
__device__ float    g_xmax[(size_t)NP * 64];
__device__ float    g_y1[(size_t)NP * 128];
__device__ double   g_st[384];
__device__ double   g_mean[192];
__device__ float    g_s0[64], g_t0[64], g_s1[128], g_t1[128];

__device__ __forceinline__ void coords_of(float x, float y, float z,
                                          int& cx, int& cy, int& cz) {
    /* XLA rewrites div-by-const to mul-by-reciprocal; 1/0.1f==10.0f, 1/0.2f==5.0f */
    cx = (int)floorf(__fmul_rn(x, 10.0f));
    cy = (int)floorf(__fmul_rn(__fadd_rn(y, 40.0f), 10.0f));
    cz = (int)floorf(__fmul_rn(__fadd_rn(z, 3.0f), 5.0f));
}
__device__ __forceinline__ unsigned long long pk2(float a, float b) {
    unsigned long long r;
    asm("mov.b64 %0,{%1,%2};" : "=l"(r) : "f"(a), "f"(b));
    return r;
}
__device__ __forceinline__ void upk(unsigned long long v, float& a, float& b) {
    asm("mov.b64 {%0,%1},%2;" : "=f"(a), "=f"(b) : "l"(v));
}
__device__ __forceinline__ unsigned long long fma2(unsigned long long a,
                                                   unsigned long long b,
                                                   unsigned long long c) {
    unsigned long long d;
    asm("fma.rn.f32x2 %0,%1,%2,%3;" : "=l"(d) : "l"(a), "l"(b), "l"(c));
    return d;
}

__global__ void k_keys(const float* __restrict__ pts) {
    int i = blockIdx.x * 256 + threadIdx.x;
    if (i >= NP) return;
    float b = pts[i * 5 + 0];
    float x = pts[i * 5 + 1], y = pts[i * 5 + 2], z = pts[i * 5 + 3];
    int cx, cy, cz;
    coords_of(x, y, z, cx, cy, cz);
    int key = (int)b * SXYZ + cx * SYZ + cy * SZ + cz;
    g_keys[i] = key;
    atomicOr(&g_bits[(unsigned)key >> 5], 1u << (key & 31));
}

__global__ void k_scan_words() {
    __shared__ unsigned sh[256];
    unsigned b = blockIdx.x, t = threadIdx.x;
    unsigned base = b * 1024u + t * 4u;
    uint4 w = make_uint4(0u, 0u, 0u, 0u);
    if (base < NWORDS) w = *(const uint4*)&g_bits[base];
    unsigned c0 = __popc(w.x), c1 = __popc(w.y), c2 = __popc(w.z), c3 = __popc(w.w);
    unsigned tot = c0 + c1 + c2 + c3;
    sh[t] = tot;
    __syncthreads();
    for (int off = 1; off < 256; off <<= 1) {
        unsigned v = (t >= (unsigned)off) ? sh[t - off] : 0u;
        __syncthreads();
        sh[t] += v;
        __syncthreads();
    }
    unsigned excl = sh[t] - tot;
    if (base < NWORDS) {
        g_wpre[base + 0] = excl;
        g_wpre[base + 1] = excl + c0;
        g_wpre[base + 2] = excl + c0 + c1;
        g_wpre[base + 3] = excl + c0 + c1 + c2;
    }
    if (t == 255) g_bsum[b] = sh[255];
}

__global__ void k_scan_blocks() {
    __shared__ unsigned sh[1024];
    int t = threadIdx.x;
    unsigned v = (t < SCAN_BLOCKS) ? g_bsum[t] : 0u;
    sh[t] = v;
    __syncthreads();
    for (int off = 1; off < 1024; off <<= 1) {
        unsigned u = (t >= off) ? sh[t - off] : 0u;
        __syncthreads();
        sh[t] += u;
        __syncthreads();
    }
    if (t < SCAN_BLOCKS) g_boff[t] = sh[t] - v;
}

__global__ void k_inv(const float* __restrict__ pts) {
    int i = blockIdx.x * 256 + threadIdx.x;
    if (i >= NP) return;
    int key = g_keys[i];
    unsigned w = (unsigned)key >> 5, bit = key & 31;
    unsigned rank = g_boff[w >> 10] + g_wpre[w] +
                    __popc(g_bits[w] & ((1u << bit) - 1u));
    g_inv[i] = (int)rank;
    atomicAdd(&g_cnt[rank], 1);
    atomicAdd(&g_sums[rank * 3 + 0], pts[i * 5 + 1]);
    atomicAdd(&g_sums[rank * 3 + 1], pts[i * 5 + 2]);
    atomicAdd(&g_sums[rank * 3 + 2], pts[i * 5 + 3]);
}

__global__ void k_fillcoords(float* __restrict__ oc) {
    int i = blockIdx.x * 256 + threadIdx.x;
    if (i >= NP) return;
    ((float4*)oc)[i] = make_float4(-1.f, 19.f, 799.f, 703.f);
}

__global__ void k_coords(float* __restrict__ oc) {
    int w = blockIdx.x * 256 + threadIdx.x;
    if (w >= NWORDS) return;
    unsigned m = g_bits[w];
    if (!m) return;
    unsigned r = g_boff[w >> 10] + g_wpre[w];
    int kb = w << 5;
    while (m) {
        int b = __ffs(m) - 1;
        m &= m - 1;
        int key = kb + b;
        int B = key / SXYZ;
        int rem = key % SXYZ;
        int X = rem / SYZ; rem -= X * SYZ;
        int Y = rem / SZ;
        int Z = rem - Y * SZ;
        ((float4*)oc)[r] = make_float4((float)B, (float)Z, (float)Y, (float)X);
        r++;
    }
}

__global__ void k_layer0(const float* __restrict__ pts, const float* __restrict__ W0) {
    __shared__ float w0s[640];
    int tid = threadIdx.x;
    for (int j = tid; j < 640; j += 256) w0s[j] = W0[j];
    __syncthreads();
    int i = blockIdx.x * 256 + tid;
    if (i >= NP) return;
    float x = pts[i * 5 + 1], y = pts[i * 5 + 2], z = pts[i * 5 + 3];
    float inten = pts[i * 5 + 4];
    int cx, cy, cz;
    coords_of(x, y, z, cx, cy, cz);
    int seg = g_inv[i];
    float cnt = fmaxf((float)g_cnt[seg], 1.f);
    float f[10];
    f[0] = x;
    f[1] = y;
    f[2] = z;
    f[3] = inten;
    f[4] = __fsub_rn(x, __fdiv_rn(g_sums[seg * 3 + 0], cnt));
    f[5] = __fsub_rn(y, __fdiv_rn(g_sums[seg * 3 + 1], cnt));
    f[6] = __fsub_rn(z, __fdiv_rn(g_sums[seg * 3 + 2], cnt));
    f[7] = __fsub_rn(x, __fadd_rn(__fmul_rn((float)cx, 0.1f), OFF0));
    f[8] = __fsub_rn(y, __fadd_rn(__fmul_rn((float)cy, 0.1f), OFF1));
    f[9] = __fsub_rn(z, __fadd_rn(__fmul_rn((float)cz, 0.2f), OFF2));
    #pragma unroll 4
    for (int c = 0; c < 64; c++) {
        float a = 0.f;
        #pragma unroll
        for (int k = 0; k < 10; k++) a = fmaf(f[k], w0s[k * 64 + c], a);
        g_y0[(size_t)c * NP + i] = a;
    }
}

__global__ void k_sum0() {
    int c = blockIdx.y;
    const float* col = &g_y0[(size_t)c * NP];
    int start = blockIdx.x * 12500;
    double s = 0.0;
    for (int j = start + threadIdx.x; j < start + 12500; j += 256)
        s += (double)col[j];
    for (int o = 16; o; o >>= 1) s += __shfl_down_sync(0xffffffffu, s, o);
    __shared__ double as[8];
    int w = threadIdx.x >> 5, l = threadIdx.x & 31;
    if (l == 0) as[w] = s;
    __syncthreads();
    if (threadIdx.x == 0) {
        double S = 0;
        for (int i = 0; i < 8; i++) S += as[i];
        atomicAdd(&g_st[c], S);
    }
}
__global__ void k_mean0() {
    int c = threadIdx.x;
    if (c < 64) g_mean[c] = g_st[c] / (double)NP;
}
__global__ void k_var0() {
    int c = blockIdx.y;
    const float* col = &g_y0[(size_t)c * NP];
    double m = g_mean[c];
    int start = blockIdx.x * 12500;
    double s = 0.0;
    for (int j = start + threadIdx.x; j < start + 12500; j += 256) {
        double d = (double)col[j] - m;
        s += d * d;
    }
    for (int o = 16; o; o >>= 1) s += __shfl_down_sync(0xffffffffu, s, o);
    __shared__ double as[8];
    int w = threadIdx.x >> 5, l = threadIdx.x & 31;
    if (l == 0) as[w] = s;
    __syncthreads();
    if (threadIdx.x == 0) {
        double S = 0;
        for (int i = 0; i < 8; i++) S += as[i];
        atomicAdd(&g_st[64 + c], S);
    }
}
__global__ void k_bn0(const float* __restrict__ g, const float* __restrict__ b) {
    int c = threadIdx.x;
    if (c >= 64) return;
    double var = g_st[64 + c] / (double)NP;
    double s = (double)g[c] / sqrt(var + 0.001);
    g_s0[c] = (float)s;
    g_t0[c] = (float)((double)b[c] - g_mean[c] * s);
}

__global__ void k_xmax() {
    __shared__ float sS[64], sT[64];
    int tid = threadIdx.x;
    if (tid < 64) { sS[tid] = g_s0[tid]; sT[tid] = g_t0[tid]; }
    __syncthreads();
    int i = blockIdx.x * 256 + tid;
    if (i >= NP) return;
    int seg = g_inv[i];
    int* dst = (int*)&g_xmax[(size_t)seg * 64];
    #pragma unroll 8
    for (int c = 0; c < 64; c++) {
        float v = g_y0[(size_t)c * NP + i];
        float h = fmaxf(fmaf(v, sS[c], sT[c]), 0.f);
        atomicMax(&dst[c], __float_as_int(h));
    }
}

__global__ void __launch_bounds__(256, 1) k_gemm1(const float* __restrict__ W1) {
    extern __shared__ float sh[];
    float* ws = sh;
    float* xs = sh + 16384;
    __shared__ float sS[64], sT[64];
    int tid = threadIdx.x;
    if (tid < 64)  { sS[tid] = g_s0[tid]; sT[tid] = g_t0[tid]; }
    const float4* w4 = (const float4*)W1;
    float4* ws4 = (float4*)ws;
    for (int j = tid; j < 4096; j += 256) ws4[j] = w4[j];
    __syncthreads();

    int bs = blockIdx.x * 128;
    for (int idx = tid; idx < 8192; idx += 256) {
        int k = idx >> 7, m = idx & 127;
        float v = g_y0[(size_t)k * NP + bs + m];
        xs[k * 132 + m] = fmaxf(fmaf(v, sS[k], sT[k]), 0.f);
    }
    {
        int m = tid & 127, half = tid >> 7;
        int seg = g_inv[bs + m];
        const float4* src = (const float4*)&g_xmax[(size_t)seg * 64 + half * 32];
        #pragma unroll
        for (int q = 0; q < 8; q++) {
            float4 v = src[q];
            int k0 = 64 + half * 32 + q * 4;
            xs[(k0 + 0) * 132 + m] = v.x;
            xs[(k0 + 1) * 132 + m] = v.y;
            xs[(k0 + 2) * 132 + m] = v.z;
            xs[(k0 + 3) * 132 + m] = v.w;
        }
    }
    __syncthreads();

    int tx = tid & 15, ty = tid >> 4;
    unsigned long long acc[8][4];
    #pragma unroll
    for (int i = 0; i < 8; i++)
        #pragma unroll
        for (int p = 0; p < 4; p++) acc[i][p] = 0ull;

    #pragma unroll 2
    for (int k = 0; k < 128; k++) {
        float4 a0 = *(const float4*)&xs[k * 132 + ty * 8];
        float4 a1 = *(const float4*)&xs[k * 132 + ty * 8 + 4];
        unsigned long long am[8];
        am[0] = pk2(a0.x, a0.x); am[1] = pk2(a0.y, a0.y);
        am[2] = pk2(a0.z, a0.z); am[3] = pk2(a0.w, a0.w);
        am[4] = pk2(a1.x, a1.x); am[5] = pk2(a1.y, a1.y);
        am[6] = pk2(a1.z, a1.z); am[7] = pk2(a1.w, a1.w);
        ulonglong2 b0 = *(const ulonglong2*)&ws[k * 128 + tx * 8];
        ulonglong2 b1 = *(const ulonglong2*)&ws[k * 128 + tx * 8 + 4];
        #pragma unroll
        for (int i = 0; i < 8; i++) {
            acc[i][0] = fma2(am[i], b0.x, acc[i][0]);
            acc[i][1] = fma2(am[i], b0.y, acc[i][1]);
            acc[i][2] = fma2(am[i], b1.x, acc[i][2]);
            acc[i][3] = fma2(am[i], b1.y, acc[i][3]);
        }
    }

    #pragma unroll
    for (int i = 0; i < 8; i++) {
        float v[8];
        #pragma unroll
        for (int p = 0; p < 4; p++) upk(acc[i][p], v[2 * p], v[2 * p + 1]);
        int pt = bs + ty * 8 + i;
        float4* dst = (float4*)&g_y1[(size_t)pt * 128 + tx * 8];
        dst[0] = make_float4(v[0], v[1], v[2], v[3]);
        dst[1] = make_float4(v[4], v[5], v[6], v[7]);
    }
}

__global__ void k_sum1() {
    int c = threadIdx.x;
    size_t r0 = (size_t)blockIdx.x * 1000;
    double s = 0.0;
    for (int r = 0; r < 1000; r++)
        s += (double)g_y1[(r0 + r) * 128 + c];
    atomicAdd(&g_st[128 + c], s);
}
__global__ void k_mean1() {
    int c = threadIdx.x;
    if (c < 128) g_mean[64 + c] = g_st[128 + c] / (double)NP;
}
__global__ void k_var1() {
    int c = threadIdx.x;
    double m = g_mean[64 + c];
    size_t r0 = (size_t)blockIdx.x * 1000;
    double s = 0.0;
    for (int r = 0; r < 1000; r++) {
        double d = (double)g_y1[(r0 + r) * 128 + c] - m;
        s += d * d;
    }
    atomicAdd(&g_st[256 + c], s);
}
__global__ void k_bn1(const float* __restrict__ g, const float* __restrict__ b) {
    int c = threadIdx.x;
    if (c >= 128) return;
    double var = g_st[256 + c] / (double)NP;
    double s = (double)g[c] / sqrt(var + 0.001);
    g_s1[c] = (float)s;
    g_t1[c] = (float)((double)b[c] - g_mean[64 + c] * s);
}

__global__ void k_final(float* __restrict__ out) {
    __shared__ float s1[128], t1[128];
    int tid = threadIdx.x;
    s1[tid] = g_s1[tid];
    t1[tid] = g_t1[tid];
    __syncthreads();
    int q = tid & 3;
    int p = blockIdx.x * 32 + (tid >> 2);
    int seg = g_inv[p];
    int* ob = (int*)&out[(size_t)seg * 128];
    const float4* yr = (const float4*)&g_y1[(size_t)p * 128];
    #pragma unroll
    for (int r = 0; r < 8; r++) {
        int c = r * 16 + q * 4;
        float4 v = yr[c >> 2];
        atomicMax(&ob[c + 0], __float_as_int(fmaxf(fmaf(v.x, s1[c + 0], t1[c + 0]), 0.f)));
        atomicMax(&ob[c + 1], __float_as_int(fmaxf(fmaf(v.y, s1[c + 1], t1[c + 1]), 0.f)));
        atomicMax(&ob[c + 2], __float_as_int(fmaxf(fmaf(v.z, s1[c + 2], t1[c + 2]), 0.f)));
        atomicMax(&ob[c + 3], __float_as_int(fmaxf(fmaf(v.w, s1[c + 3], t1[c + 3]), 0.f)));
    }
}

extern "C" void kernel_launch(void* const* d_in, const int* in_sizes, int n_in,
                              void* d_out, int out_size) {
    const float* pts = (const float*)d_in[0];
    const float* W0  = (const float*)d_in[1];
    const float* g0  = (const float*)d_in[2];
    const float* b0  = (const float*)d_in[3];
    const float* W1  = (const float*)d_in[4];
    const float* g1  = (const float*)d_in[5];
    const float* b1  = (const float*)d_in[6];
    float* out = (float*)d_out;
    float* oc = out + (size_t)NP * 128;
    int emit_coords = ((long long)out_size >= (long long)NP * 132);

    void *p_bits, *p_cnt, *p_sums, *p_st, *p_xmax;
    cudaGetSymbolAddress(&p_bits, g_bits);
    cudaGetSymbolAddress(&p_cnt,  g_cnt);
    cudaGetSymbolAddress(&p_sums, g_sums);
    cudaGetSymbolAddress(&p_st,   g_st);
    cudaGetSymbolAddress(&p_xmax, g_xmax);

    cudaMemsetAsync(p_bits, 0, NWORDS * 4);
    cudaMemsetAsync(p_cnt,  0, NP * 4);
    cudaMemsetAsync(p_sums, 0, NP * 12);
    cudaMemsetAsync(p_st,   0, 384 * 8);
    cudaMemsetAsync(p_xmax, 0, (size_t)NP * 64 * 4);
    cudaMemsetAsync(out,    0, (size_t)NP * 128 * 4);

    k_keys<<<1563, 256>>>(pts);
    k_scan_words<<<SCAN_BLOCKS, 256>>>();
    k_scan_blocks<<<1, 1024>>>();
    k_inv<<<1563, 256>>>(pts);
    if (emit_coords) {
        k_fillcoords<<<1563, 256>>>(oc);
        k_coords<<<2750, 256>>>(oc);
    }
    k_layer0<<<1563, 256>>>(pts, W0);
    {
        dim3 g(32, 64);
        k_sum0<<<g, 256>>>();
        k_mean0<<<1, 64>>>();
        k_var0<<<g, 256>>>();
    }
    k_bn0<<<1, 64>>>(g0, b0);
    k_xmax<<<1563, 256>>>();
    cudaFuncSetAttribute(k_gemm1, cudaFuncAttributeMaxDynamicSharedMemorySize, 133120);
    k_gemm1<<<3125, 256, 133120>>>(W1);
    k_sum1<<<400, 128>>>();
    k_mean1<<<1, 128>>>();
    k_var1<<<400, 128>>>();
    k_bn1<<<1, 128>>>(g1, b1);
    k_final<<<12500, 128>>>(out);
}

// round 8
// speedup vs baseline: 2.0091x; 2.0091x over previous
#include <cuda_runtime.h>

#define NP 400000
#define SXYZ 11264000
#define SYZ 16000
#define SZ 20
#define NWORDS 704000
#define SCAN_BLOCKS 688

#define OFF0 (0.05f)
#define OFF1 (0.05f - 40.0f)
#define OFF2 (0.1f - 3.0f)

__device__ unsigned g_bits[NWORDS];
__device__ unsigned g_wpre[NWORDS];
__device__ unsigned g_bsum[SCAN_BLOCKS];
__device__ unsigned g_boff[SCAN_BLOCKS];
__device__ int      g_nuniq;
__device__ int      g_keys[NP];
__device__ int      g_inv[NP];
__device__ int      g_cnt[NP];
__device__ float    g_sums[NP * 3];
__device__ float    g_y0[(size_t)64 * NP];      /* col-major [64][N] */
__device__ unsigned g_xmaxu[(size_t)NP * 64];   /* row-major, order-preserving uint */
__device__ float    g_y1[(size_t)NP * 128];     /* row-major */
__device__ double   g_st[384];
__device__ float    g_s0[64], g_t0[64], g_s1[128], g_t1[128];

__device__ __forceinline__ void coords_of(float x, float y, float z,
                                          int& cx, int& cy, int& cz) {
    cx = (int)floorf(__fmul_rn(x, 10.0f));
    cy = (int)floorf(__fmul_rn(__fadd_rn(y, 40.0f), 10.0f));
    cz = (int)floorf(__fmul_rn(__fadd_rn(z, 3.0f), 5.0f));
}
__device__ __forceinline__ unsigned utrans(float x) {
    unsigned u = __float_as_uint(x);
    return (u & 0x80000000u) ? ~u : (u | 0x80000000u);
}
__device__ __forceinline__ float uinv(unsigned u) {
    return __uint_as_float((u & 0x80000000u) ? (u & 0x7fffffffu) : ~u);
}
__device__ __forceinline__ unsigned long long pk2(float a, float b) {
    unsigned long long r;
    asm("mov.b64 %0,{%1,%2};" : "=l"(r) : "f"(a), "f"(b));
    return r;
}
__device__ __forceinline__ void upk(unsigned long long v, float& a, float& b) {
    asm("mov.b64 {%0,%1},%2;" : "=f"(a), "=f"(b) : "l"(v));
}
__device__ __forceinline__ unsigned long long fma2(unsigned long long a,
                                                   unsigned long long b,
                                                   unsigned long long c) {
    unsigned long long d;
    asm("fma.rn.f32x2 %0,%1,%2,%3;" : "=l"(d) : "l"(a), "l"(b), "l"(c));
    return d;
}

__global__ void k_keys(const float* __restrict__ pts) {
    int i = blockIdx.x * 256 + threadIdx.x;
    if (i >= NP) return;
    float b = pts[i * 5 + 0];
    float x = pts[i * 5 + 1], y = pts[i * 5 + 2], z = pts[i * 5 + 3];
    int cx, cy, cz;
    coords_of(x, y, z, cx, cy, cz);
    int key = (int)b * SXYZ + cx * SYZ + cy * SZ + cz;
    g_keys[i] = key;
    atomicOr(&g_bits[(unsigned)key >> 5], 1u << (key & 31));
}

__global__ void k_scan_words() {
    __shared__ unsigned sh[256];
    unsigned b = blockIdx.x, t = threadIdx.x;
    unsigned base = b * 1024u + t * 4u;
    uint4 w = make_uint4(0u, 0u, 0u, 0u);
    if (base < NWORDS) w = *(const uint4*)&g_bits[base];
    unsigned c0 = __popc(w.x), c1 = __popc(w.y), c2 = __popc(w.z), c3 = __popc(w.w);
    unsigned tot = c0 + c1 + c2 + c3;
    sh[t] = tot;
    __syncthreads();
    for (int off = 1; off < 256; off <<= 1) {
        unsigned v = (t >= (unsigned)off) ? sh[t - off] : 0u;
        __syncthreads();
        sh[t] += v;
        __syncthreads();
    }
    unsigned excl = sh[t] - tot;
    if (base < NWORDS) {
        g_wpre[base + 0] = excl;
        g_wpre[base + 1] = excl + c0;
        g_wpre[base + 2] = excl + c0 + c1;
        g_wpre[base + 3] = excl + c0 + c1 + c2;
    }
    if (t == 255) g_bsum[b] = sh[255];
}

__global__ void k_scan_blocks() {
    __shared__ unsigned sh[1024];
    int t = threadIdx.x;
    unsigned v = (t < SCAN_BLOCKS) ? g_bsum[t] : 0u;
    sh[t] = v;
    __syncthreads();
    for (int off = 1; off < 1024; off <<= 1) {
        unsigned u = (t >= off) ? sh[t - off] : 0u;
        __syncthreads();
        sh[t] += u;
        __syncthreads();
    }
    if (t < SCAN_BLOCKS) g_boff[t] = sh[t] - v;
    if (t == 1023) g_nuniq = (int)sh[1023];
}

__global__ void k_inv(const float* __restrict__ pts) {
    int i = blockIdx.x * 256 + threadIdx.x;
    if (i >= NP) return;
    int key = g_keys[i];
    unsigned w = (unsigned)key >> 5, bit = key & 31;
    unsigned rank = g_boff[w >> 10] + g_wpre[w] +
                    __popc(g_bits[w] & ((1u << bit) - 1u));
    g_inv[i] = (int)rank;
    atomicAdd(&g_cnt[rank], 1);
    atomicAdd(&g_sums[rank * 3 + 0], pts[i * 5 + 1]);
    atomicAdd(&g_sums[rank * 3 + 1], pts[i * 5 + 2]);
    atomicAdd(&g_sums[rank * 3 + 2], pts[i * 5 + 3]);
}

/* zero only what the fast store path won't fully overwrite:
   out rows for tail (rank>=nuniq) and multi-point segments;
   xmaxu rows for multi-point segments (0 == utrans(-inf)). */
__global__ void k_zero(float* __restrict__ out) {
    int i = blockIdx.x * 256 + threadIdx.x;
    if (i >= NP) return;
    int nu = g_nuniq;
    bool multi = (i < nu) && (g_cnt[i] > 1);
    if (i >= nu || multi) {
        float4* o = (float4*)&out[(size_t)i * 128];
        #pragma unroll
        for (int q = 0; q < 32; q++) o[q] = make_float4(0.f, 0.f, 0.f, 0.f);
    }
    if (multi) {
        uint4* xm = (uint4*)&g_xmaxu[(size_t)i * 64];
        #pragma unroll
        for (int q = 0; q < 16; q++) xm[q] = make_uint4(0u, 0u, 0u, 0u);
    }
}

__global__ void k_fillcoords(float* __restrict__ oc) {
    int i = blockIdx.x * 256 + threadIdx.x;
    if (i >= NP || i < g_nuniq) return;
    ((float4*)oc)[i] = make_float4(-1.f, 19.f, 799.f, 703.f);
}

__global__ void k_coords(float* __restrict__ oc) {
    int w = blockIdx.x * 256 + threadIdx.x;
    if (w >= NWORDS) return;
    unsigned m = g_bits[w];
    if (!m) return;
    unsigned r = g_boff[w >> 10] + g_wpre[w];
    int kb = w << 5;
    while (m) {
        int b = __ffs(m) - 1;
        m &= m - 1;
        int key = kb + b;
        int B = key / SXYZ;
        int rem = key % SXYZ;
        int X = rem / SYZ; rem -= X * SYZ;
        int Y = rem / SZ;
        int Z = rem - Y * SZ;
        ((float4*)oc)[r] = make_float4((float)B, (float)Z, (float)Y, (float)X);
        r++;
    }
}

__global__ void k_layer0(const float* __restrict__ pts, const float* __restrict__ W0) {
    __shared__ float w0s[640];
    int tid = threadIdx.x;
    for (int j = tid; j < 640; j += 256) w0s[j] = W0[j];
    __syncthreads();
    int i = blockIdx.x * 256 + tid;
    if (i >= NP) return;
    float x = pts[i * 5 + 1], y = pts[i * 5 + 2], z = pts[i * 5 + 3];
    float inten = pts[i * 5 + 4];
    int cx, cy, cz;
    coords_of(x, y, z, cx, cy, cz);
    int seg = g_inv[i];
    int cnt = g_cnt[seg];
    float fc = fmaxf((float)cnt, 1.f);
    float f[10];
    f[0] = x;
    f[1] = y;
    f[2] = z;
    f[3] = inten;
    f[4] = __fsub_rn(x, __fdiv_rn(g_sums[seg * 3 + 0], fc));
    f[5] = __fsub_rn(y, __fdiv_rn(g_sums[seg * 3 + 1], fc));
    f[6] = __fsub_rn(z, __fdiv_rn(g_sums[seg * 3 + 2], fc));
    f[7] = __fsub_rn(x, __fadd_rn(__fmul_rn((float)cx, 0.1f), OFF0));
    f[8] = __fsub_rn(y, __fadd_rn(__fmul_rn((float)cy, 0.1f), OFF1));
    f[9] = __fsub_rn(z, __fadd_rn(__fmul_rn((float)cz, 0.2f), OFF2));
    float a[64];
    #pragma unroll
    for (int c = 0; c < 64; c++) {
        float acc = 0.f;
        #pragma unroll
        for (int k = 0; k < 10; k++) acc = fmaf(f[k], w0s[k * 64 + c], acc);
        a[c] = acc;
        g_y0[(size_t)c * NP + i] = acc;
    }
    if (cnt == 1) {
        #pragma unroll
        for (int q = 0; q < 16; q++) {
            uint4 u;
            u.x = utrans(a[q * 4 + 0]);
            u.y = utrans(a[q * 4 + 1]);
            u.z = utrans(a[q * 4 + 2]);
            u.w = utrans(a[q * 4 + 3]);
            *(uint4*)&g_xmaxu[(size_t)seg * 64 + q * 4] = u;
        }
    } else {
        #pragma unroll
        for (int c = 0; c < 64; c++)
            atomicMax(&g_xmaxu[(size_t)seg * 64 + c], utrans(a[c]));
    }
}

/* single-pass sum + sumsq per column of y0 */
__global__ void k_stats0() {
    int c = blockIdx.y;
    const float* col = &g_y0[(size_t)c * NP];
    int start = blockIdx.x * 12500;
    double s = 0.0, s2 = 0.0;
    for (int j = start + threadIdx.x; j < start + 12500; j += 256) {
        double v = (double)col[j];
        s += v;
        s2 += v * v;
    }
    for (int o = 16; o; o >>= 1) {
        s  += __shfl_down_sync(0xffffffffu, s,  o);
        s2 += __shfl_down_sync(0xffffffffu, s2, o);
    }
    __shared__ double as[8], as2[8];
    int w = threadIdx.x >> 5, l = threadIdx.x & 31;
    if (l == 0) { as[w] = s; as2[w] = s2; }
    __syncthreads();
    if (threadIdx.x == 0) {
        double S = 0, S2 = 0;
        for (int i = 0; i < 8; i++) { S += as[i]; S2 += as2[i]; }
        atomicAdd(&g_st[c], S);
        atomicAdd(&g_st[64 + c], S2);
    }
}
__global__ void k_bn0(const float* __restrict__ g, const float* __restrict__ b) {
    int c = threadIdx.x;
    if (c >= 64) return;
    double m = g_st[c] / (double)NP;
    double var = g_st[64 + c] / (double)NP - m * m;
    double s = (double)g[c] / sqrt(var + 0.001);
    g_s0[c] = (float)s;
    g_t0[c] = (float)((double)b[c] - m * s);
}

__global__ void __launch_bounds__(256, 1) k_gemm1(const float* __restrict__ W1) {
    extern __shared__ float sh[];
    float* ws = sh;            /* 128*128 */
    float* xs = sh + 16384;    /* 128*132 */
    __shared__ float sS[64], sT[64];
    int tid = threadIdx.x;
    if (tid < 64)  { sS[tid] = g_s0[tid]; sT[tid] = g_t0[tid]; }
    const float4* w4 = (const float4*)W1;
    float4* ws4 = (float4*)ws;
    for (int j = tid; j < 4096; j += 256) ws4[j] = w4[j];
    __syncthreads();

    int bs = blockIdx.x * 128;
    for (int idx = tid; idx < 8192; idx += 256) {
        int k = idx >> 7, m = idx & 127;
        float v = g_y0[(size_t)k * NP + bs + m];
        xs[k * 132 + m] = fmaxf(fmaf(v, sS[k], sT[k]), 0.f);
    }
    {
        int m = tid & 127, half = tid >> 7;
        int seg = g_inv[bs + m];
        const uint4* src = (const uint4*)&g_xmaxu[(size_t)seg * 64 + half * 32];
        #pragma unroll
        for (int q = 0; q < 8; q++) {
            uint4 u = src[q];
            int j = half * 32 + q * 4;
            int k0 = 64 + j;
            xs[(k0 + 0) * 132 + m] = fmaxf(fmaf(uinv(u.x), sS[j + 0], sT[j + 0]), 0.f);
            xs[(k0 + 1) * 132 + m] = fmaxf(fmaf(uinv(u.y), sS[j + 1], sT[j + 1]), 0.f);
            xs[(k0 + 2) * 132 + m] = fmaxf(fmaf(uinv(u.z), sS[j + 2], sT[j + 2]), 0.f);
            xs[(k0 + 3) * 132 + m] = fmaxf(fmaf(uinv(u.w), sS[j + 3], sT[j + 3]), 0.f);
        }
    }
    __syncthreads();

    int tx = tid & 15, ty = tid >> 4;
    unsigned long long acc[8][4];
    #pragma unroll
    for (int i = 0; i < 8; i++)
        #pragma unroll
        for (int p = 0; p < 4; p++) acc[i][p] = 0ull;

    #pragma unroll 2
    for (int k = 0; k < 128; k++) {
        float4 a0 = *(const float4*)&xs[k * 132 + ty * 8];
        float4 a1 = *(const float4*)&xs[k * 132 + ty * 8 + 4];
        unsigned long long am[8];
        am[0] = pk2(a0.x, a0.x); am[1] = pk2(a0.y, a0.y);
        am[2] = pk2(a0.z, a0.z); am[3] = pk2(a0.w, a0.w);
        am[4] = pk2(a1.x, a1.x); am[5] = pk2(a1.y, a1.y);
        am[6] = pk2(a1.z, a1.z); am[7] = pk2(a1.w, a1.w);
        ulonglong2 b0 = *(const ulonglong2*)&ws[k * 128 + tx * 8];
        ulonglong2 b1 = *(const ulonglong2*)&ws[k * 128 + tx * 8 + 4];
        #pragma unroll
        for (int i = 0; i < 8; i++) {
            acc[i][0] = fma2(am[i], b0.x, acc[i][0]);
            acc[i][1] = fma2(am[i], b0.y, acc[i][1]);
            acc[i][2] = fma2(am[i], b1.x, acc[i][2]);
            acc[i][3] = fma2(am[i], b1.y, acc[i][3]);
        }
    }

    float cs[8] = {0,0,0,0,0,0,0,0}, cs2[8] = {0,0,0,0,0,0,0,0};
    #pragma unroll
    for (int i = 0; i < 8; i++) {
        float v[8];
        #pragma unroll
        for (int p = 0; p < 4; p++) upk(acc[i][p], v[2 * p], v[2 * p + 1]);
        int pt = bs + ty * 8 + i;
        float4* dst = (float4*)&g_y1[(size_t)pt * 128 + tx * 8];
        dst[0] = make_float4(v[0], v[1], v[2], v[3]);
        dst[1] = make_float4(v[4], v[5], v[6], v[7]);
        #pragma unroll
        for (int j = 0; j < 8; j++) { cs[j] += v[j]; cs2[j] += v[j] * v[j]; }
    }
    /* block-level column stats: stage partials in xs (done with GEMM reads) */
    __syncthreads();
    #pragma unroll
    for (int j = 0; j < 8; j++) xs[ty * 128 + tx * 8 + j] = cs[j];
    __syncthreads();
    if (tid < 128) {
        float s = 0.f;
        #pragma unroll
        for (int r = 0; r < 16; r++) s += xs[r * 128 + tid];
        atomicAdd(&g_st[128 + tid], (double)s);
    }
    __syncthreads();
    #pragma unroll
    for (int j = 0; j < 8; j++) xs[ty * 128 + tx * 8 + j] = cs2[j];
    __syncthreads();
    if (tid < 128) {
        float s = 0.f;
        #pragma unroll
        for (int r = 0; r < 16; r++) s += xs[r * 128 + tid];
        atomicAdd(&g_st[256 + tid], (double)s);
    }
}

__global__ void k_bn1(const float* __restrict__ g, const float* __restrict__ b) {
    int c = threadIdx.x;
    if (c >= 128) return;
    double m = g_st[128 + c] / (double)NP;
    double var = g_st[256 + c] / (double)NP - m * m;
    double s = (double)g[c] / sqrt(var + 0.001);
    g_s1[c] = (float)s;
    g_t1[c] = (float)((double)b[c] - m * s);
}

__global__ void k_final(float* __restrict__ out) {
    __shared__ float s1[128], t1[128];
    int tid = threadIdx.x;
    if (tid < 128) { s1[tid] = g_s1[tid]; t1[tid] = g_t1[tid]; }
    __syncthreads();
    int warp = tid >> 5, lane = tid & 31;
    int pbase = blockIdx.x * 64 + warp * 8;
    float4 sv = *(const float4*)&s1[lane * 4];
    float4 tv = *(const float4*)&t1[lane * 4];
    #pragma unroll
    for (int pp = 0; pp < 8; pp++) {
        int p = pbase + pp;
        int seg = g_inv[p];
        int cnt = g_cnt[seg];
        float4 v = *(const float4*)&g_y1[(size_t)p * 128 + lane * 4];
        float4 h;
        h.x = fmaxf(fmaf(v.x, sv.x, tv.x), 0.f);
        h.y = fmaxf(fmaf(v.y, sv.y, tv.y), 0.f);
        h.z = fmaxf(fmaf(v.z, sv.z, tv.z), 0.f);
        h.w = fmaxf(fmaf(v.w, sv.w, tv.w), 0.f);
        if (cnt == 1) {
            *(float4*)&out[(size_t)seg * 128 + lane * 4] = h;
        } else {
            int* ob = (int*)&out[(size_t)seg * 128 + lane * 4];
            atomicMax(&ob[0], __float_as_int(h.x));
            atomicMax(&ob[1], __float_as_int(h.y));
            atomicMax(&ob[2], __float_as_int(h.z));
            atomicMax(&ob[3], __float_as_int(h.w));
        }
    }
}

extern "C" void kernel_launch(void* const* d_in, const int* in_sizes, int n_in,
                              void* d_out, int out_size) {
    const float* pts = (const float*)d_in[0];
    const float* W0  = (const float*)d_in[1];
    const float* g0  = (const float*)d_in[2];
    const float* b0  = (const float*)d_in[3];
    const float* W1  = (const float*)d_in[4];
    const float* g1  = (const float*)d_in[5];
    const float* b1  = (const float*)d_in[6];
    float* out = (float*)d_out;
    float* oc = out + (size_t)NP * 128;
    int emit_coords = ((long long)out_size >= (long long)NP * 132);

    void *p_bits, *p_cnt, *p_sums, *p_st;
    cudaGetSymbolAddress(&p_bits, g_bits);
    cudaGetSymbolAddress(&p_cnt,  g_cnt);
    cudaGetSymbolAddress(&p_sums, g_sums);
    cudaGetSymbolAddress(&p_st,   g_st);

    cudaMemsetAsync(p_bits, 0, NWORDS * 4);
    cudaMemsetAsync(p_cnt,  0, NP * 4);
    cudaMemsetAsync(p_sums, 0, NP * 12);
    cudaMemsetAsync(p_st,   0, 384 * 8);

    k_keys<<<1563, 256>>>(pts);
    k_scan_words<<<SCAN_BLOCKS, 256>>>();
    k_scan_blocks<<<1, 1024>>>();
    k_inv<<<1563, 256>>>(pts);
    k_zero<<<1563, 256>>>(out);
    if (emit_coords) {
        k_fillcoords<<<1563, 256>>>(oc);
        k_coords<<<2750, 256>>>(oc);
    }
    k_layer0<<<1563, 256>>>(pts, W0);
    {
        dim3 g(32, 64);
        k_stats0<<<g, 256>>>();
    }
    k_bn0<<<1, 64>>>(g0, b0);
    cudaFuncSetAttribute(k_gemm1, cudaFuncAttributeMaxDynamicSharedMemorySize, 133120);
    k_gemm1<<<3125, 256, 133120>>>(W1);
    k_bn1<<<1, 128>>>(g1, b1);
    k_final<<<6250, 256>>>(out);
}

// round 9
// speedup vs baseline: 3.4346x; 1.7095x over previous
#include <cuda_runtime.h>

#define NP 400000
#define SXYZ 11264000
#define SYZ 16000
#define SZ 20
#define NWORDS 704000
#define SCAN_BLOCKS 688

#define OFF0 (0.05f)
#define OFF1 (0.05f - 40.0f)
#define OFF2 (0.1f - 3.0f)

__device__ unsigned g_bits[NWORDS];
__device__ unsigned g_wpre[NWORDS];
__device__ unsigned g_bsum[SCAN_BLOCKS];
__device__ unsigned g_boff[SCAN_BLOCKS];
__device__ int      g_nuniq;
__device__ int      g_nmulti;
__device__ int      g_mlist[NP];
__device__ int      g_keys[NP];
__device__ int      g_inv[NP];
__device__ int      g_cnt[NP];
__device__ float    g_sums[NP * 3];
__device__ float    g_y0[(size_t)64 * NP];      /* col-major [64][N] */
__device__ unsigned g_xmaxu[(size_t)NP * 64];   /* row-major; only multi segs used */
__device__ float    g_y1[(size_t)NP * 128];     /* row-major */
__device__ float    g_wsum[8192];               /* W1a + W1b  [64][128] */
__device__ double   g_st[384];
__device__ float    g_s0[64], g_t0[64], g_s1[128], g_t1[128];

__device__ __forceinline__ void coords_of(float x, float y, float z,
                                          int& cx, int& cy, int& cz) {
    cx = (int)floorf(__fmul_rn(x, 10.0f));
    cy = (int)floorf(__fmul_rn(__fadd_rn(y, 40.0f), 10.0f));
    cz = (int)floorf(__fmul_rn(__fadd_rn(z, 3.0f), 5.0f));
}
__device__ __forceinline__ unsigned utrans(float x) {
    unsigned u = __float_as_uint(x);
    return (u & 0x80000000u) ? ~u : (u | 0x80000000u);
}
__device__ __forceinline__ float uinv(unsigned u) {
    return __uint_as_float((u & 0x80000000u) ? (u & 0x7fffffffu) : ~u);
}
__device__ __forceinline__ unsigned long long pk2(float a, float b) {
    unsigned long long r;
    asm("mov.b64 %0,{%1,%2};" : "=l"(r) : "f"(a), "f"(b));
    return r;
}
__device__ __forceinline__ void upk(unsigned long long v, float& a, float& b) {
    asm("mov.b64 {%0,%1},%2;" : "=f"(a), "=f"(b) : "l"(v));
}
__device__ __forceinline__ unsigned long long fma2(unsigned long long a,
                                                   unsigned long long b,
                                                   unsigned long long c) {
    unsigned long long d;
    asm("fma.rn.f32x2 %0,%1,%2,%3;" : "=l"(d) : "l"(a), "l"(b), "l"(c));
    return d;
}

__global__ void k_keys(const float* __restrict__ pts) {
    int i = blockIdx.x * 256 + threadIdx.x;
    if (i >= NP) return;
    float b = pts[i * 5 + 0];
    float x = pts[i * 5 + 1], y = pts[i * 5 + 2], z = pts[i * 5 + 3];
    int cx, cy, cz;
    coords_of(x, y, z, cx, cy, cz);
    int key = (int)b * SXYZ + cx * SYZ + cy * SZ + cz;
    g_keys[i] = key;
    atomicOr(&g_bits[(unsigned)key >> 5], 1u << (key & 31));
}

__global__ void k_scan_words() {
    __shared__ unsigned sh[256];
    unsigned b = blockIdx.x, t = threadIdx.x;
    unsigned base = b * 1024u + t * 4u;
    uint4 w = make_uint4(0u, 0u, 0u, 0u);
    if (base < NWORDS) w = *(const uint4*)&g_bits[base];
    unsigned c0 = __popc(w.x), c1 = __popc(w.y), c2 = __popc(w.z), c3 = __popc(w.w);
    unsigned tot = c0 + c1 + c2 + c3;
    sh[t] = tot;
    __syncthreads();
    for (int off = 1; off < 256; off <<= 1) {
        unsigned v = (t >= (unsigned)off) ? sh[t - off] : 0u;
        __syncthreads();
        sh[t] += v;
        __syncthreads();
    }
    unsigned excl = sh[t] - tot;
    if (base < NWORDS) {
        g_wpre[base + 0] = excl;
        g_wpre[base + 1] = excl + c0;
        g_wpre[base + 2] = excl + c0 + c1;
        g_wpre[base + 3] = excl + c0 + c1 + c2;
    }
    if (t == 255) g_bsum[b] = sh[255];
}

__global__ void k_scan_blocks() {
    __shared__ unsigned sh[1024];
    int t = threadIdx.x;
    unsigned v = (t < SCAN_BLOCKS) ? g_bsum[t] : 0u;
    sh[t] = v;
    __syncthreads();
    for (int off = 1; off < 1024; off <<= 1) {
        unsigned u = (t >= off) ? sh[t - off] : 0u;
        __syncthreads();
        sh[t] += u;
        __syncthreads();
    }
    if (t < SCAN_BLOCKS) g_boff[t] = sh[t] - v;
    if (t == 1023) g_nuniq = (int)sh[1023];
}

__global__ void k_inv(const float* __restrict__ pts) {
    int i = blockIdx.x * 256 + threadIdx.x;
    if (i >= NP) return;
    int key = g_keys[i];
    unsigned w = (unsigned)key >> 5, bit = key & 31;
    unsigned rank = g_boff[w >> 10] + g_wpre[w] +
                    __popc(g_bits[w] & ((1u << bit) - 1u));
    g_inv[i] = (int)rank;
    atomicAdd(&g_cnt[rank], 1);
    atomicAdd(&g_sums[rank * 3 + 0], pts[i * 5 + 1]);
    atomicAdd(&g_sums[rank * 3 + 1], pts[i * 5 + 2]);
    atomicAdd(&g_sums[rank * 3 + 2], pts[i * 5 + 3]);
}

__global__ void k_zero(float* __restrict__ out) {
    int i = blockIdx.x * 256 + threadIdx.x;
    if (i >= NP) return;
    int nu = g_nuniq;
    bool multi = (i < nu) && (g_cnt[i] > 1);
    if (i >= nu || multi) {
        float4* o = (float4*)&out[(size_t)i * 128];
        #pragma unroll
        for (int q = 0; q < 32; q++) o[q] = make_float4(0.f, 0.f, 0.f, 0.f);
    }
    if (multi) {
        uint4* xm = (uint4*)&g_xmaxu[(size_t)i * 64];
        #pragma unroll
        for (int q = 0; q < 16; q++) xm[q] = make_uint4(0u, 0u, 0u, 0u);
    }
}

__global__ void k_fillcoords(float* __restrict__ oc) {
    int i = blockIdx.x * 256 + threadIdx.x;
    if (i >= NP || i < g_nuniq) return;
    ((float4*)oc)[i] = make_float4(-1.f, 19.f, 799.f, 703.f);
}

__global__ void k_coords(float* __restrict__ oc) {
    int w = blockIdx.x * 256 + threadIdx.x;
    if (w >= NWORDS) return;
    unsigned m = g_bits[w];
    if (!m) return;
    unsigned r = g_boff[w >> 10] + g_wpre[w];
    int kb = w << 5;
    while (m) {
        int b = __ffs(m) - 1;
        m &= m - 1;
        int key = kb + b;
        int B = key / SXYZ;
        int rem = key % SXYZ;
        int X = rem / SYZ; rem -= X * SYZ;
        int Y = rem / SZ;
        int Z = rem - Y * SZ;
        ((float4*)oc)[r] = make_float4((float)B, (float)Z, (float)Y, (float)X);
        r++;
    }
}

__global__ void k_wsum(const float* __restrict__ W1) {
    int j = blockIdx.x * 256 + threadIdx.x;
    if (j < 8192) g_wsum[j] = W1[j] + W1[j + 8192];
}

__global__ void k_layer0(const float* __restrict__ pts, const float* __restrict__ W0) {
    __shared__ float w0s[640];
    __shared__ float ss[64], ss2[64];
    int tid = threadIdx.x;
    for (int j = tid; j < 640; j += 256) w0s[j] = W0[j];
    if (tid < 64) { ss[tid] = 0.f; ss2[tid] = 0.f; }
    __syncthreads();
    int i = blockIdx.x * 256 + tid;
    bool valid = i < NP;
    float f[10] = {0.f,0.f,0.f,0.f,0.f,0.f,0.f,0.f,0.f,0.f};
    int seg = 0, cnt = 1;
    if (valid) {
        float x = pts[i * 5 + 1], y = pts[i * 5 + 2], z = pts[i * 5 + 3];
        float inten = pts[i * 5 + 4];
        int cx, cy, cz;
        coords_of(x, y, z, cx, cy, cz);
        seg = g_inv[i];
        cnt = g_cnt[seg];
        float fc = fmaxf((float)cnt, 1.f);
        f[0] = x; f[1] = y; f[2] = z; f[3] = inten;
        f[4] = __fsub_rn(x, __fdiv_rn(g_sums[seg * 3 + 0], fc));
        f[5] = __fsub_rn(y, __fdiv_rn(g_sums[seg * 3 + 1], fc));
        f[6] = __fsub_rn(z, __fdiv_rn(g_sums[seg * 3 + 2], fc));
        f[7] = __fsub_rn(x, __fadd_rn(__fmul_rn((float)cx, 0.1f), OFF0));
        f[8] = __fsub_rn(y, __fadd_rn(__fmul_rn((float)cy, 0.1f), OFF1));
        f[9] = __fsub_rn(z, __fadd_rn(__fmul_rn((float)cz, 0.2f), OFF2));
    }
    float a[64];
    #pragma unroll
    for (int c = 0; c < 64; c++) {
        float acc = 0.f;
        #pragma unroll
        for (int k = 0; k < 10; k++) acc = fmaf(f[k], w0s[k * 64 + c], acc);
        a[c] = acc;
    }
    if (valid) {
        #pragma unroll 8
        for (int c = 0; c < 64; c++) g_y0[(size_t)c * NP + i] = a[c];
        if (cnt > 1) {
            #pragma unroll 8
            for (int c = 0; c < 64; c++)
                atomicMax(&g_xmaxu[(size_t)seg * 64 + c], utrans(a[c]));
            int mi = atomicAdd(&g_nmulti, 1);
            g_mlist[mi] = i;
        }
    }
    /* fused BN0 stats: warp shfl-reduce each column, then block+global */
    int lane = tid & 31;
    #pragma unroll
    for (int c = 0; c < 64; c++) {
        float v = a[c], v2 = v * v;
        #pragma unroll
        for (int o = 16; o; o >>= 1) {
            v  += __shfl_down_sync(0xffffffffu, v,  o);
            v2 += __shfl_down_sync(0xffffffffu, v2, o);
        }
        if (lane == 0) { atomicAdd(&ss[c], v); atomicAdd(&ss2[c], v2); }
    }
    __syncthreads();
    if (tid < 64) {
        atomicAdd(&g_st[tid],      (double)ss[tid]);
        atomicAdd(&g_st[64 + tid], (double)ss2[tid]);
    }
}

__global__ void k_bn0(const float* __restrict__ g, const float* __restrict__ b) {
    int c = threadIdx.x;
    if (c >= 64) return;
    double m = g_st[c] / (double)NP;
    double var = g_st[64 + c] / (double)NP - m * m;
    double s = (double)g[c] / sqrt(var + 0.001);
    g_s0[c] = (float)s;
    g_t0[c] = (float)((double)b[c] - m * s);
}

/* Pass A: y1 = h0 @ (W1a+W1b), K=64.  h0 = relu(bn0(y0)). */
__global__ void __launch_bounds__(256, 2) k_gemm1() {
    extern __shared__ float sh[];
    float* ws = sh;            /* 64*128 */
    float* xs = sh + 8192;     /* 64*132 */
    __shared__ float sS[64], sT[64];
    int tid = threadIdx.x;
    if (tid < 64)  { sS[tid] = g_s0[tid]; sT[tid] = g_t0[tid]; }
    {
        const float4* w4 = (const float4*)g_wsum;
        float4* ws4 = (float4*)ws;
        for (int j = tid; j < 2048; j += 256) ws4[j] = w4[j];
    }
    __syncthreads();

    int bs = blockIdx.x * 128;
    for (int idx = tid; idx < 8192; idx += 256) {
        int k = idx >> 7, m = idx & 127;
        float v = g_y0[(size_t)k * NP + bs + m];
        xs[k * 132 + m] = fmaxf(fmaf(v, sS[k], sT[k]), 0.f);
    }
    __syncthreads();

    int tx = tid & 15, ty = tid >> 4;
    unsigned long long acc[8][4];
    #pragma unroll
    for (int i = 0; i < 8; i++)
        #pragma unroll
        for (int p = 0; p < 4; p++) acc[i][p] = 0ull;

    #pragma unroll 2
    for (int k = 0; k < 64; k++) {
        float4 a0 = *(const float4*)&xs[k * 132 + ty * 8];
        float4 a1 = *(const float4*)&xs[k * 132 + ty * 8 + 4];
        unsigned long long am[8];
        am[0] = pk2(a0.x, a0.x); am[1] = pk2(a0.y, a0.y);
        am[2] = pk2(a0.z, a0.z); am[3] = pk2(a0.w, a0.w);
        am[4] = pk2(a1.x, a1.x); am[5] = pk2(a1.y, a1.y);
        am[6] = pk2(a1.z, a1.z); am[7] = pk2(a1.w, a1.w);
        ulonglong2 b0 = *(const ulonglong2*)&ws[k * 128 + tx * 8];
        ulonglong2 b1 = *(const ulonglong2*)&ws[k * 128 + tx * 8 + 4];
        #pragma unroll
        for (int i = 0; i < 8; i++) {
            acc[i][0] = fma2(am[i], b0.x, acc[i][0]);
            acc[i][1] = fma2(am[i], b0.y, acc[i][1]);
            acc[i][2] = fma2(am[i], b1.x, acc[i][2]);
            acc[i][3] = fma2(am[i], b1.y, acc[i][3]);
        }
    }

    float cs[8] = {0,0,0,0,0,0,0,0}, cs2[8] = {0,0,0,0,0,0,0,0};
    #pragma unroll
    for (int i = 0; i < 8; i++) {
        float v[8];
        #pragma unroll
        for (int p = 0; p < 4; p++) upk(acc[i][p], v[2 * p], v[2 * p + 1]);
        int pt = bs + ty * 8 + i;
        float4* dst = (float4*)&g_y1[(size_t)pt * 128 + tx * 8];
        dst[0] = make_float4(v[0], v[1], v[2], v[3]);
        dst[1] = make_float4(v[4], v[5], v[6], v[7]);
        #pragma unroll
        for (int j = 0; j < 8; j++) { cs[j] += v[j]; cs2[j] += v[j] * v[j]; }
    }
    __syncthreads();
    #pragma unroll
    for (int j = 0; j < 8; j++) xs[ty * 128 + tx * 8 + j] = cs[j];
    __syncthreads();
    if (tid < 128) {
        float s = 0.f;
        #pragma unroll
        for (int r = 0; r < 16; r++) s += xs[r * 128 + tid];
        atomicAdd(&g_st[128 + tid], (double)s);
    }
    __syncthreads();
    #pragma unroll
    for (int j = 0; j < 8; j++) xs[ty * 128 + tx * 8 + j] = cs2[j];
    __syncthreads();
    if (tid < 128) {
        float s = 0.f;
        #pragma unroll
        for (int r = 0; r < 16; r++) s += xs[r * 128 + tid];
        atomicAdd(&g_st[256 + tid], (double)s);
    }
}

/* Pass B: correction for multi-point segments: y1 += (hmax - h0) @ W1b */
__global__ void k_gemm1b(const float* __restrict__ W1) {
    __shared__ float d[64];
    int tid = threadIdx.x;   /* 128 */
    double ds1 = 0.0, ds2 = 0.0;
    int nm = g_nmulti;
    for (int it = blockIdx.x; it < nm; it += gridDim.x) {
        int p = g_mlist[it];
        int seg = g_inv[p];
        if (tid < 64) {
            float v = g_y0[(size_t)tid * NP + p];
            float h0 = fmaxf(fmaf(v, g_s0[tid], g_t0[tid]), 0.f);
            float hm = fmaxf(fmaf(uinv(g_xmaxu[(size_t)seg * 64 + tid]),
                                  g_s0[tid], g_t0[tid]), 0.f);
            d[tid] = hm - h0;
        }
        __syncthreads();
        float acc = 0.f;
        #pragma unroll 8
        for (int k = 0; k < 64; k++)
            acc = fmaf(d[k], W1[(64 + k) * 128 + tid], acc);
        size_t oi = (size_t)p * 128 + tid;
        float old = g_y1[oi];
        float nw = old + acc;
        g_y1[oi] = nw;
        ds1 += (double)acc;
        ds2 += (double)nw * (double)nw - (double)old * (double)old;
        __syncthreads();
    }
    atomicAdd(&g_st[128 + tid], ds1);
    atomicAdd(&g_st[256 + tid], ds2);
}

__global__ void k_bn1(const float* __restrict__ g, const float* __restrict__ b) {
    int c = threadIdx.x;
    if (c >= 128) return;
    double m = g_st[128 + c] / (double)NP;
    double var = g_st[256 + c] / (double)NP - m * m;
    double s = (double)g[c] / sqrt(var + 0.001);
    g_s1[c] = (float)s;
    g_t1[c] = (float)((double)b[c] - m * s);
}

__global__ void k_final(float* __restrict__ out) {
    __shared__ float s1[128], t1[128];
    int tid = threadIdx.x;
    if (tid < 128) { s1[tid] = g_s1[tid]; t1[tid] = g_t1[tid]; }
    __syncthreads();
    int warp = tid >> 5, lane = tid & 31;
    int pbase = blockIdx.x * 64 + warp * 8;
    float4 sv = *(const float4*)&s1[lane * 4];
    float4 tv = *(const float4*)&t1[lane * 4];
    #pragma unroll
    for (int pp = 0; pp < 8; pp++) {
        int p = pbase + pp;
        int seg = g_inv[p];
        int cnt = g_cnt[seg];
        float4 v = *(const float4*)&g_y1[(size_t)p * 128 + lane * 4];
        float4 h;
        h.x = fmaxf(fmaf(v.x, sv.x, tv.x), 0.f);
        h.y = fmaxf(fmaf(v.y, sv.y, tv.y), 0.f);
        h.z = fmaxf(fmaf(v.z, sv.z, tv.z), 0.f);
        h.w = fmaxf(fmaf(v.w, sv.w, tv.w), 0.f);
        if (cnt == 1) {
            *(float4*)&out[(size_t)seg * 128 + lane * 4] = h;
        } else {
            int* ob = (int*)&out[(size_t)seg * 128 + lane * 4];
            atomicMax(&ob[0], __float_as_int(h.x));
            atomicMax(&ob[1], __float_as_int(h.y));
            atomicMax(&ob[2], __float_as_int(h.z));
            atomicMax(&ob[3], __float_as_int(h.w));
        }
    }
}

extern "C" void kernel_launch(void* const* d_in, const int* in_sizes, int n_in,
                              void* d_out, int out_size) {
    const float* pts = (const float*)d_in[0];
    const float* W0  = (const float*)d_in[1];
    const float* g0  = (const float*)d_in[2];
    const float* b0  = (const float*)d_in[3];
    const float* W1  = (const float*)d_in[4];
    const float* g1  = (const float*)d_in[5];
    const float* b1  = (const float*)d_in[6];
    float* out = (float*)d_out;
    float* oc = out + (size_t)NP * 128;
    int emit_coords = ((long long)out_size >= (long long)NP * 132);

    void *p_bits, *p_cnt, *p_sums, *p_st, *p_nm;
    cudaGetSymbolAddress(&p_bits, g_bits);
    cudaGetSymbolAddress(&p_cnt,  g_cnt);
    cudaGetSymbolAddress(&p_sums, g_sums);
    cudaGetSymbolAddress(&p_st,   g_st);
    cudaGetSymbolAddress(&p_nm,   g_nmulti);

    cudaMemsetAsync(p_bits, 0, NWORDS * 4);
    cudaMemsetAsync(p_cnt,  0, NP * 4);
    cudaMemsetAsync(p_sums, 0, NP * 12);
    cudaMemsetAsync(p_st,   0, 384 * 8);
    cudaMemsetAsync(p_nm,   0, 4);

    k_keys<<<1563, 256>>>(pts);
    k_scan_words<<<SCAN_BLOCKS, 256>>>();
    k_scan_blocks<<<1, 1024>>>();
    k_inv<<<1563, 256>>>(pts);
    k_zero<<<1563, 256>>>(out);
    if (emit_coords) {
        k_fillcoords<<<1563, 256>>>(oc);
        k_coords<<<2750, 256>>>(oc);
    }
    k_wsum<<<32, 256>>>(W1);
    k_layer0<<<1563, 256>>>(pts, W0);
    k_bn0<<<1, 64>>>(g0, b0);
    cudaFuncSetAttribute(k_gemm1, cudaFuncAttributeMaxDynamicSharedMemorySize, 66560);
    k_gemm1<<<3125, 256, 66560>>>();
    k_gemm1b<<<592, 128>>>(W1);
    k_bn1<<<1, 128>>>(g1, b1);
    k_final<<<6250, 256>>>(out);
}

// round 10
// speedup vs baseline: 4.1248x; 1.2009x over previous
#include <cuda_runtime.h>

#define NP 400000
#define SXYZ 11264000
#define SYZ 16000
#define SZ 20
#define NWORDS 704000
#define SCAN_BLOCKS 688

#define OFF0 (0.05f)
#define OFF1 (0.05f - 40.0f)
#define OFF2 (0.1f - 3.0f)

__device__ unsigned g_bits[NWORDS];
__device__ unsigned g_wpre[NWORDS];
__device__ unsigned g_bsum[SCAN_BLOCKS];
__device__ unsigned g_boff[SCAN_BLOCKS];
__device__ int      g_nuniq;
__device__ int      g_nmulti;
__device__ int      g_mlist[NP];
__device__ int      g_keys[NP];
__device__ int      g_inv[NP];
__device__ int      g_cnt[NP];
__device__ float    g_sums[NP * 3];
__device__ unsigned g_xmaxu[(size_t)NP * 64];   /* only multi segs used */
__device__ float    g_y1[(size_t)NP * 128];
__device__ float    g_wsum[8192];               /* W1a + W1b */
__device__ double   g_mom[65];                  /* Sf[10], Sff[55] */
__device__ double   g_st[384];                  /* [128:256) sum1, [256:384) sumsq1 */
__device__ float    g_s0[64], g_t0[64], g_s1[128], g_t1[128];

__device__ __forceinline__ void coords_of(float x, float y, float z,
                                          int& cx, int& cy, int& cz) {
    cx = (int)floorf(__fmul_rn(x, 10.0f));
    cy = (int)floorf(__fmul_rn(__fadd_rn(y, 40.0f), 10.0f));
    cz = (int)floorf(__fmul_rn(__fadd_rn(z, 3.0f), 5.0f));
}
__device__ __forceinline__ unsigned utrans(float x) {
    unsigned u = __float_as_uint(x);
    return (u & 0x80000000u) ? ~u : (u | 0x80000000u);
}
__device__ __forceinline__ float uinv(unsigned u) {
    return __uint_as_float((u & 0x80000000u) ? (u & 0x7fffffffu) : ~u);
}
__device__ __forceinline__ unsigned long long pk2(float a, float b) {
    unsigned long long r;
    asm("mov.b64 %0,{%1,%2};" : "=l"(r) : "f"(a), "f"(b));
    return r;
}
__device__ __forceinline__ void upk(unsigned long long v, float& a, float& b) {
    asm("mov.b64 {%0,%1},%2;" : "=f"(a), "=f"(b) : "l"(v));
}
__device__ __forceinline__ unsigned long long fma2(unsigned long long a,
                                                   unsigned long long b,
                                                   unsigned long long c) {
    unsigned long long d;
    asm("fma.rn.f32x2 %0,%1,%2,%3;" : "=l"(d) : "l"(a), "l"(b), "l"(c));
    return d;
}

/* shared exact feature recompute: identical fmaf-free op chain in all kernels */
__device__ __forceinline__ void compute_feat(const float* __restrict__ pts,
                                             int i, float* f,
                                             int& seg, int& cnt) {
    float x = pts[i * 5 + 1], y = pts[i * 5 + 2], z = pts[i * 5 + 3];
    float inten = pts[i * 5 + 4];
    int cx, cy, cz;
    coords_of(x, y, z, cx, cy, cz);
    seg = g_inv[i];
    cnt = g_cnt[seg];
    float fc = fmaxf((float)cnt, 1.f);
    f[0] = x; f[1] = y; f[2] = z; f[3] = inten;
    f[4] = __fsub_rn(x, __fdiv_rn(g_sums[seg * 3 + 0], fc));
    f[5] = __fsub_rn(y, __fdiv_rn(g_sums[seg * 3 + 1], fc));
    f[6] = __fsub_rn(z, __fdiv_rn(g_sums[seg * 3 + 2], fc));
    f[7] = __fsub_rn(x, __fadd_rn(__fmul_rn((float)cx, 0.1f), OFF0));
    f[8] = __fsub_rn(y, __fadd_rn(__fmul_rn((float)cy, 0.1f), OFF1));
    f[9] = __fsub_rn(z, __fadd_rn(__fmul_rn((float)cz, 0.2f), OFF2));
}

__global__ void k_keys(const float* __restrict__ pts) {
    int i = blockIdx.x * 256 + threadIdx.x;
    if (i >= NP) return;
    float b = pts[i * 5 + 0];
    float x = pts[i * 5 + 1], y = pts[i * 5 + 2], z = pts[i * 5 + 3];
    int cx, cy, cz;
    coords_of(x, y, z, cx, cy, cz);
    int key = (int)b * SXYZ + cx * SYZ + cy * SZ + cz;
    g_keys[i] = key;
    atomicOr(&g_bits[(unsigned)key >> 5], 1u << (key & 31));
}

__global__ void k_scan_words() {
    __shared__ unsigned sh[256];
    unsigned b = blockIdx.x, t = threadIdx.x;
    unsigned base = b * 1024u + t * 4u;
    uint4 w = make_uint4(0u, 0u, 0u, 0u);
    if (base < NWORDS) w = *(const uint4*)&g_bits[base];
    unsigned c0 = __popc(w.x), c1 = __popc(w.y), c2 = __popc(w.z), c3 = __popc(w.w);
    unsigned tot = c0 + c1 + c2 + c3;
    sh[t] = tot;
    __syncthreads();
    for (int off = 1; off < 256; off <<= 1) {
        unsigned v = (t >= (unsigned)off) ? sh[t - off] : 0u;
        __syncthreads();
        sh[t] += v;
        __syncthreads();
    }
    unsigned excl = sh[t] - tot;
    if (base < NWORDS) {
        g_wpre[base + 0] = excl;
        g_wpre[base + 1] = excl + c0;
        g_wpre[base + 2] = excl + c0 + c1;
        g_wpre[base + 3] = excl + c0 + c1 + c2;
    }
    if (t == 255) g_bsum[b] = sh[255];
}

__global__ void k_scan_blocks() {
    __shared__ unsigned sh[1024];
    int t = threadIdx.x;
    unsigned v = (t < SCAN_BLOCKS) ? g_bsum[t] : 0u;
    sh[t] = v;
    __syncthreads();
    for (int off = 1; off < 1024; off <<= 1) {
        unsigned u = (t >= off) ? sh[t - off] : 0u;
        __syncthreads();
        sh[t] += u;
        __syncthreads();
    }
    if (t < SCAN_BLOCKS) g_boff[t] = sh[t] - v;
    if (t == 1023) g_nuniq = (int)sh[1023];
}

__global__ void k_inv(const float* __restrict__ pts) {
    int i = blockIdx.x * 256 + threadIdx.x;
    if (i >= NP) return;
    int key = g_keys[i];
    unsigned w = (unsigned)key >> 5, bit = key & 31;
    unsigned rank = g_boff[w >> 10] + g_wpre[w] +
                    __popc(g_bits[w] & ((1u << bit) - 1u));
    g_inv[i] = (int)rank;
    atomicAdd(&g_cnt[rank], 1);
    atomicAdd(&g_sums[rank * 3 + 0], pts[i * 5 + 1]);
    atomicAdd(&g_sums[rank * 3 + 1], pts[i * 5 + 2]);
    atomicAdd(&g_sums[rank * 3 + 2], pts[i * 5 + 3]);
}

__global__ void k_zero(float* __restrict__ out) {
    int i = blockIdx.x * 256 + threadIdx.x;
    if (i >= NP) return;
    int nu = g_nuniq;
    bool multi = (i < nu) && (g_cnt[i] > 1);
    if (i >= nu || multi) {
        float4* o = (float4*)&out[(size_t)i * 128];
        #pragma unroll
        for (int q = 0; q < 32; q++) o[q] = make_float4(0.f, 0.f, 0.f, 0.f);
    }
    if (multi) {
        uint4* xm = (uint4*)&g_xmaxu[(size_t)i * 64];
        #pragma unroll
        for (int q = 0; q < 16; q++) xm[q] = make_uint4(0u, 0u, 0u, 0u);
    }
}

__global__ void k_fillcoords(float* __restrict__ oc) {
    int i = blockIdx.x * 256 + threadIdx.x;
    if (i >= NP || i < g_nuniq) return;
    ((float4*)oc)[i] = make_float4(-1.f, 19.f, 799.f, 703.f);
}

__global__ void k_coords(float* __restrict__ oc) {
    int w = blockIdx.x * 256 + threadIdx.x;
    if (w >= NWORDS) return;
    unsigned m = g_bits[w];
    if (!m) return;
    unsigned r = g_boff[w >> 10] + g_wpre[w];
    int kb = w << 5;
    while (m) {
        int b = __ffs(m) - 1;
        m &= m - 1;
        int key = kb + b;
        int B = key / SXYZ;
        int rem = key % SXYZ;
        int X = rem / SYZ; rem -= X * SYZ;
        int Y = rem / SZ;
        int Z = rem - Y * SZ;
        ((float4*)oc)[r] = make_float4((float)B, (float)Z, (float)Y, (float)X);
        r++;
    }
}

__global__ void k_wsum(const float* __restrict__ W1) {
    int j = blockIdx.x * 256 + threadIdx.x;
    if (j < 8192) g_wsum[j] = W1[j] + W1[j + 8192];
}

/* feature moments + multi-seg xmax; NO y0 materialization */
__global__ void __launch_bounds__(256) k_prep(const float* __restrict__ pts,
                                              const float* __restrict__ W0) {
    __shared__ float w0s[640];
    __shared__ float sm[65];
    int tid = threadIdx.x;
    for (int j = tid; j < 640; j += 256) w0s[j] = W0[j];
    if (tid < 65) sm[tid] = 0.f;
    __syncthreads();
    float mom[65];
    #pragma unroll
    for (int v = 0; v < 65; v++) mom[v] = 0.f;
    int base = blockIdx.x * 2048;
    for (int i = base + tid; i < base + 2048 && i < NP; i += 256) {
        float f[10];
        int seg, cnt;
        compute_feat(pts, i, f, seg, cnt);
        #pragma unroll
        for (int k = 0; k < 10; k++) mom[k] += f[k];
        {
            int idx = 10;
            #pragma unroll
            for (int k = 0; k < 10; k++)
                #pragma unroll
                for (int l = k; l < 10; l++)
                    mom[idx++] += f[k] * f[l];
        }
        if (cnt > 1) {
            int mi = atomicAdd(&g_nmulti, 1);
            g_mlist[mi] = i;
            unsigned* xm = &g_xmaxu[(size_t)seg * 64];
            #pragma unroll 8
            for (int c = 0; c < 64; c++) {
                float acc = 0.f;
                #pragma unroll
                for (int k = 0; k < 10; k++) acc = fmaf(f[k], w0s[k * 64 + c], acc);
                atomicMax(&xm[c], utrans(acc));
            }
        }
    }
    int lane = tid & 31;
    #pragma unroll
    for (int v = 0; v < 65; v++) {
        float s = mom[v];
        #pragma unroll
        for (int o = 16; o; o >>= 1) s += __shfl_down_sync(0xffffffffu, s, o);
        if (lane == 0) atomicAdd(&sm[v], s);
    }
    __syncthreads();
    if (tid < 65) atomicAdd(&g_mom[tid], (double)sm[tid]);
}

/* BN0 stats by bilinearity of moments */
__global__ void k_bn0(const float* __restrict__ W0,
                      const float* __restrict__ g, const float* __restrict__ b) {
    int c = threadIdx.x;
    if (c >= 64) return;
    double w[10];
    #pragma unroll
    for (int k = 0; k < 10; k++) w[k] = (double)W0[k * 64 + c];
    double mean = 0.0;
    #pragma unroll
    for (int k = 0; k < 10; k++) mean += w[k] * g_mom[k];
    mean /= (double)NP;
    double ey2 = 0.0;
    int idx = 10;
    #pragma unroll
    for (int k = 0; k < 10; k++)
        #pragma unroll
        for (int l = k; l < 10; l++) {
            double t = w[k] * w[l] * g_mom[idx++];
            ey2 += (k == l) ? t : 2.0 * t;
        }
    ey2 /= (double)NP;
    double var = ey2 - mean * mean;
    double s = (double)g[c] / sqrt(var + 0.001);
    g_s0[c] = (float)s;
    g_t0[c] = (float)((double)b[c] - mean * s);
}

/* Pass A: y1 = h0 @ (W1a+W1b), h0 recomputed from pts (no y0) */
__global__ void __launch_bounds__(256, 2) k_gemm1(const float* __restrict__ pts,
                                                  const float* __restrict__ W0) {
    extern __shared__ float sh[];
    float* ws = sh;            /* 64*128 */
    float* xs = sh + 8192;     /* 64*132 */
    __shared__ float w0s[640];
    __shared__ float sS[64], sT[64];
    int tid = threadIdx.x;
    if (tid < 64)  { sS[tid] = g_s0[tid]; sT[tid] = g_t0[tid]; }
    for (int j = tid; j < 640; j += 256) w0s[j] = W0[j];
    {
        const float4* w4 = (const float4*)g_wsum;
        float4* ws4 = (float4*)ws;
        for (int j = tid; j < 2048; j += 256) ws4[j] = w4[j];
    }
    __syncthreads();

    int bs = blockIdx.x * 128;
    {
        int m = tid & 127, half = tid >> 7;
        float f[10];
        int seg, cnt;
        compute_feat(pts, bs + m, f, seg, cnt);
        int cbase = half * 32;
        #pragma unroll 8
        for (int c = cbase; c < cbase + 32; c++) {
            float acc = 0.f;
            #pragma unroll
            for (int k = 0; k < 10; k++) acc = fmaf(f[k], w0s[k * 64 + c], acc);
            xs[c * 132 + m] = fmaxf(fmaf(acc, sS[c], sT[c]), 0.f);
        }
    }
    __syncthreads();

    int tx = tid & 15, ty = tid >> 4;
    unsigned long long acc[8][4];
    #pragma unroll
    for (int i = 0; i < 8; i++)
        #pragma unroll
        for (int p = 0; p < 4; p++) acc[i][p] = 0ull;

    #pragma unroll 2
    for (int k = 0; k < 64; k++) {
        float4 a0 = *(const float4*)&xs[k * 132 + ty * 8];
        float4 a1 = *(const float4*)&xs[k * 132 + ty * 8 + 4];
        unsigned long long am[8];
        am[0] = pk2(a0.x, a0.x); am[1] = pk2(a0.y, a0.y);
        am[2] = pk2(a0.z, a0.z); am[3] = pk2(a0.w, a0.w);
        am[4] = pk2(a1.x, a1.x); am[5] = pk2(a1.y, a1.y);
        am[6] = pk2(a1.z, a1.z); am[7] = pk2(a1.w, a1.w);
        ulonglong2 b0 = *(const ulonglong2*)&ws[k * 128 + tx * 8];
        ulonglong2 b1 = *(const ulonglong2*)&ws[k * 128 + tx * 8 + 4];
        #pragma unroll
        for (int i = 0; i < 8; i++) {
            acc[i][0] = fma2(am[i], b0.x, acc[i][0]);
            acc[i][1] = fma2(am[i], b0.y, acc[i][1]);
            acc[i][2] = fma2(am[i], b1.x, acc[i][2]);
            acc[i][3] = fma2(am[i], b1.y, acc[i][3]);
        }
    }

    float cs[8] = {0,0,0,0,0,0,0,0}, cs2[8] = {0,0,0,0,0,0,0,0};
    #pragma unroll
    for (int i = 0; i < 8; i++) {
        float v[8];
        #pragma unroll
        for (int p = 0; p < 4; p++) upk(acc[i][p], v[2 * p], v[2 * p + 1]);
        int pt = bs + ty * 8 + i;
        float4* dst = (float4*)&g_y1[(size_t)pt * 128 + tx * 8];
        dst[0] = make_float4(v[0], v[1], v[2], v[3]);
        dst[1] = make_float4(v[4], v[5], v[6], v[7]);
        #pragma unroll
        for (int j = 0; j < 8; j++) { cs[j] += v[j]; cs2[j] += v[j] * v[j]; }
    }
    __syncthreads();
    #pragma unroll
    for (int j = 0; j < 8; j++) xs[ty * 128 + tx * 8 + j] = cs[j];
    __syncthreads();
    if (tid < 128) {
        float s = 0.f;
        #pragma unroll
        for (int r = 0; r < 16; r++) s += xs[r * 128 + tid];
        atomicAdd(&g_st[128 + tid], (double)s);
    }
    __syncthreads();
    #pragma unroll
    for (int j = 0; j < 8; j++) xs[ty * 128 + tx * 8 + j] = cs2[j];
    __syncthreads();
    if (tid < 128) {
        float s = 0.f;
        #pragma unroll
        for (int r = 0; r < 16; r++) s += xs[r * 128 + tid];
        atomicAdd(&g_st[256 + tid], (double)s);
    }
}

/* Pass B: multi-seg correction y1 += (hmax - h0) @ W1b, h0 recomputed */
__global__ void k_gemm1b(const float* __restrict__ pts,
                         const float* __restrict__ W0,
                         const float* __restrict__ W1) {
    __shared__ float w0s[640];
    __shared__ float d[64];
    int tid = threadIdx.x;   /* 128 */
    for (int j = tid; j < 640; j += 128) w0s[j] = W0[j];
    __syncthreads();
    double ds1 = 0.0, ds2 = 0.0;
    int nm = g_nmulti;
    for (int it = blockIdx.x; it < nm; it += gridDim.x) {
        int p = g_mlist[it];
        float f[10];
        int seg, cnt;
        compute_feat(pts, p, f, seg, cnt);
        if (tid < 64) {
            float acc = 0.f;
            #pragma unroll
            for (int k = 0; k < 10; k++) acc = fmaf(f[k], w0s[k * 64 + tid], acc);
            float h0 = fmaxf(fmaf(acc, g_s0[tid], g_t0[tid]), 0.f);
            float hm = fmaxf(fmaf(uinv(g_xmaxu[(size_t)seg * 64 + tid]),
                                  g_s0[tid], g_t0[tid]), 0.f);
            d[tid] = hm - h0;
        }
        __syncthreads();
        float acc = 0.f;
        #pragma unroll 8
        for (int k = 0; k < 64; k++)
            acc = fmaf(d[k], W1[(64 + k) * 128 + tid], acc);
        size_t oi = (size_t)p * 128 + tid;
        float old = g_y1[oi];
        float nw = old + acc;
        g_y1[oi] = nw;
        ds1 += (double)acc;
        ds2 += (double)nw * (double)nw - (double)old * (double)old;
        __syncthreads();
    }
    atomicAdd(&g_st[128 + tid], ds1);
    atomicAdd(&g_st[256 + tid], ds2);
}

__global__ void k_bn1(const float* __restrict__ g, const float* __restrict__ b) {
    int c = threadIdx.x;
    if (c >= 128) return;
    double m = g_st[128 + c] / (double)NP;
    double var = g_st[256 + c] / (double)NP - m * m;
    double s = (double)g[c] / sqrt(var + 0.001);
    g_s1[c] = (float)s;
    g_t1[c] = (float)((double)b[c] - m * s);
}

__global__ void k_final(float* __restrict__ out) {
    __shared__ float s1[128], t1[128];
    int tid = threadIdx.x;
    if (tid < 128) { s1[tid] = g_s1[tid]; t1[tid] = g_t1[tid]; }
    __syncthreads();
    int warp = tid >> 5, lane = tid & 31;
    int pbase = blockIdx.x * 64 + warp * 8;
    float4 sv = *(const float4*)&s1[lane * 4];
    float4 tv = *(const float4*)&t1[lane * 4];
    #pragma unroll
    for (int pp = 0; pp < 8; pp++) {
        int p = pbase + pp;
        int seg = g_inv[p];
        int cnt = g_cnt[seg];
        float4 v = *(const float4*)&g_y1[(size_t)p * 128 + lane * 4];
        float4 h;
        h.x = fmaxf(fmaf(v.x, sv.x, tv.x), 0.f);
        h.y = fmaxf(fmaf(v.y, sv.y, tv.y), 0.f);
        h.z = fmaxf(fmaf(v.z, sv.z, tv.z), 0.f);
        h.w = fmaxf(fmaf(v.w, sv.w, tv.w), 0.f);
        if (cnt == 1) {
            *(float4*)&out[(size_t)seg * 128 + lane * 4] = h;
        } else {
            int* ob = (int*)&out[(size_t)seg * 128 + lane * 4];
            atomicMax(&ob[0], __float_as_int(h.x));
            atomicMax(&ob[1], __float_as_int(h.y));
            atomicMax(&ob[2], __float_as_int(h.z));
            atomicMax(&ob[3], __float_as_int(h.w));
        }
    }
}

extern "C" void kernel_launch(void* const* d_in, const int* in_sizes, int n_in,
                              void* d_out, int out_size) {
    const float* pts = (const float*)d_in[0];
    const float* W0  = (const float*)d_in[1];
    const float* g0  = (const float*)d_in[2];
    const float* b0  = (const float*)d_in[3];
    const float* W1  = (const float*)d_in[4];
    const float* g1  = (const float*)d_in[5];
    const float* b1  = (const float*)d_in[6];
    float* out = (float*)d_out;
    float* oc = out + (size_t)NP * 128;
    int emit_coords = ((long long)out_size >= (long long)NP * 132);

    void *p_bits, *p_cnt, *p_sums, *p_st, *p_nm, *p_mom;
    cudaGetSymbolAddress(&p_bits, g_bits);
    cudaGetSymbolAddress(&p_cnt,  g_cnt);
    cudaGetSymbolAddress(&p_sums, g_sums);
    cudaGetSymbolAddress(&p_st,   g_st);
    cudaGetSymbolAddress(&p_nm,   g_nmulti);
    cudaGetSymbolAddress(&p_mom,  g_mom);

    cudaMemsetAsync(p_bits, 0, NWORDS * 4);
    cudaMemsetAsync(p_cnt,  0, NP * 4);
    cudaMemsetAsync(p_sums, 0, NP * 12);
    cudaMemsetAsync(p_st,   0, 384 * 8);
    cudaMemsetAsync(p_nm,   0, 4);
    cudaMemsetAsync(p_mom,  0, 65 * 8);

    k_keys<<<1563, 256>>>(pts);
    k_scan_words<<<SCAN_BLOCKS, 256>>>();
    k_scan_blocks<<<1, 1024>>>();
    k_inv<<<1563, 256>>>(pts);
    k_zero<<<1563, 256>>>(out);
    if (emit_coords) {
        k_fillcoords<<<1563, 256>>>(oc);
        k_coords<<<2750, 256>>>(oc);
    }
    k_wsum<<<32, 256>>>(W1);
    k_prep<<<196, 256>>>(pts, W0);
    k_bn0<<<1, 64>>>(W0, g0, b0);
    cudaFuncSetAttribute(k_gemm1, cudaFuncAttributeMaxDynamicSharedMemorySize, 66560);
    k_gemm1<<<3125, 256, 66560>>>(pts, W0);
    k_gemm1b<<<592, 128>>>(pts, W0, W1);
    k_bn1<<<1, 128>>>(g1, b1);
    k_final<<<6250, 256>>>(out);
}